// round 1
// baseline (speedup 1.0000x reference)
#include <cuda_runtime.h>

#define BATCH 1024
#define NEL 32
#define NUP 16
#define NION 8
#define D1 256
#define D2 32
#define DION 64
#define DELION 32
#define EMB 64
#define FEAT 928
#define MULT_ELEMS (BATCH*NEL*NEL*EMB)   // 67108864

// Scratch (allocation-free rule: __device__ globals)
__device__ float g_hmapped[BATCH*NEL*EMB];       // 8 MB
__device__ float g_hionm[BATCH*NION*DELION];     // 1 MB
__device__ float g_avg[BATCH*2*D1];              // 2 MB

// Accurate-enough fast tanh: 2 MUFU + few ALU, rel err ~1e-6
__device__ __forceinline__ float fast_tanh(float x) {
    float ax = fabsf(x);
    float e  = __expf(-2.0f * ax);
    float r  = __fdividef(1.0f - e, 1.0f + e);
    return copysignf(r, x);
}

// ---------------------------------------------------------------------------
// K1: h_mapped[b,i,e] = tanh(h_one[b,i,:] @ W_hmap + b_hmap), plus avg_up/dn
// grid=B, block=256. h_one[b] (32KB) in smem; W streamed via L1 (__ldg).
// ---------------------------------------------------------------------------
__global__ void __launch_bounds__(256) k1_hmap(
    const float* __restrict__ h_one,
    const float* __restrict__ W,      // (256,64)
    const float* __restrict__ bias)   // (64,)
{
    __shared__ float sH[NEL*D1];   // 32 KB
    int b = blockIdx.x;
    const float* hb = h_one + (size_t)b*NEL*D1;
    for (int t = threadIdx.x; t < NEL*D1; t += 256) sH[t] = hb[t];
    __syncthreads();

    int e = threadIdx.x & 63;
    int g = threadIdx.x >> 6;      // 0..3 -> rows g*8 .. g*8+7
    float acc[8];
    float bv = __ldg(bias + e);
    #pragma unroll
    for (int r = 0; r < 8; r++) acc[r] = bv;

    const float* Wc = W + e;
    #pragma unroll 4
    for (int k = 0; k < D1; k++) {
        float w = __ldg(Wc + k*EMB);
        #pragma unroll
        for (int r = 0; r < 8; r++)
            acc[r] = fmaf(sH[(g*8 + r)*D1 + k], w, acc[r]);
    }
    float* o = g_hmapped + (size_t)b*NEL*EMB;
    #pragma unroll
    for (int r = 0; r < 8; r++)
        o[(g*8 + r)*EMB + e] = fast_tanh(acc[r]);

    // spin-averages of h_one (for tile_up/tile_dn)
    int d = threadIdx.x;           // 0..255 == D1
    float su = 0.f, sd = 0.f;
    #pragma unroll
    for (int i = 0; i < NUP; i++)  su += sH[i*D1 + d];
    #pragma unroll
    for (int i = NUP; i < NEL; i++) sd += sH[i*D1 + d];
    g_avg[(size_t)b*2*D1 + d]      = su * (1.0f/NUP);
    g_avg[(size_t)b*2*D1 + D1 + d] = sd * (1.0f/(NEL - NUP));
}

// ---------------------------------------------------------------------------
// K1b: h_ion_mapped[b,a,c] = tanh(h_ion[b,a,:] @ W_ion + b_ion)
// grid=B, block=256 (8 ions x 32 out)
// ---------------------------------------------------------------------------
__global__ void __launch_bounds__(256) k1_ion(
    const float* __restrict__ h_ion,   // (B,8,64)
    const float* __restrict__ W,       // (64,32)
    const float* __restrict__ bias)    // (32,)
{
    __shared__ float sI[NION*DION];
    int b = blockIdx.x;
    const float* ib = h_ion + (size_t)b*NION*DION;
    for (int t = threadIdx.x; t < NION*DION; t += 256) sI[t] = ib[t];
    __syncthreads();

    int c = threadIdx.x & 31;
    int a = threadIdx.x >> 5;    // 0..7
    float acc = __ldg(bias + c);
    #pragma unroll 4
    for (int k = 0; k < DION; k++)
        acc = fmaf(sI[a*DION + k], __ldg(W + k*DELION + c), acc);
    g_hionm[((size_t)b*NION + a)*DELION + c] = fast_tanh(acc);
}

// ---------------------------------------------------------------------------
// K2: pair GEMM + tanh + multiply, writes el_el_mult, el_el, f_pairs.
// grid=B, block=256. Per i-row: load 32x32 pair tile, each thread owns
// (e = tid&63, j = tid>>6 + 4*jj). FFMA-pipe bound (~126us floor).
// ---------------------------------------------------------------------------
__global__ void __launch_bounds__(256) k2_pairs(
    const float* __restrict__ h_el_el,
    const float* __restrict__ Wsame, const float* __restrict__ bsame,
    const float* __restrict__ Wdiff, const float* __restrict__ bdiff,
    float* __restrict__ feats, float* __restrict__ mult)
{
    __shared__ float sW[2][D2*EMB];        // 16 KB (same, diff)
    __shared__ float sBias[2][EMB];
    __shared__ float sHM[NEL*EMB];         // 8 KB
    __shared__ __align__(16) float sPair[NEL*D2];  // 4 KB
    __shared__ float sRed[256];

    int b = blockIdx.x;
    for (int t = threadIdx.x; t < D2*EMB; t += 256) {
        sW[0][t] = Wsame[t];
        sW[1][t] = Wdiff[t];
    }
    if (threadIdx.x < EMB) {
        sBias[0][threadIdx.x] = bsame[threadIdx.x];
        sBias[1][threadIdx.x] = bdiff[threadIdx.x];
    }
    const float* hm = g_hmapped + (size_t)b*NEL*EMB;
    for (int t = threadIdx.x; t < NEL*EMB; t += 256) sHM[t] = hm[t];

    int e  = threadIdx.x & 63;
    int j0 = threadIdx.x >> 6;   // 0..3
    const float* pb = h_el_el + (size_t)b*NEL*NEL*D2;

    for (int i = 0; i < NEL; i++) {
        __syncthreads();   // protect sPair/sRed from previous iteration readers
        ((float4*)sPair)[threadIdx.x] =
            ((const float4*)(pb + (size_t)i*NEL*D2))[threadIdx.x];
        __syncthreads();

        int iu = (i < NUP) ? 0 : 1;
        float accEl = 0.f;
        float* mrow = mult + (((size_t)b*NEL + i)*NEL)*EMB;
        #pragma unroll
        for (int jj = 0; jj < 8; jj++) {
            int j = j0 + jj*4;
            int sel = ((j < NUP) ? 0 : 1) ^ iu;   // 0 = same spin, 1 = diff
            const float* Wp = sW[sel];
            const float* pr = sPair + j*D2;
            float acc = sBias[sel][e];
            #pragma unroll
            for (int k = 0; k < D2; k++)
                acc = fmaf(pr[k], Wp[k*EMB + e], acc);
            float o = fast_tanh(acc) * sHM[j*EMB + e];
            mrow[j*EMB + e] = o;
            accEl += o;
        }
        sRed[threadIdx.x] = accEl;
        __syncthreads();

        float* fb = feats + (((size_t)b*NEL + i)*FEAT);
        if (threadIdx.x < 64) {
            // el_el[b,i,e] = mean_{j<16} + mean_{j>=16} = sum_all / 16
            float s = sRed[threadIdx.x] + sRed[64 + threadIdx.x]
                    + sRed[128 + threadIdx.x] + sRed[192 + threadIdx.x];
            fb[832 + threadIdx.x] = s * (1.0f/16.0f);
        } else if (threadIdx.x < 128) {
            // f_pairs_up / f_pairs_dn from the raw pair tile
            int t = threadIdx.x - 64;
            int half = t >> 5;
            int c = t & 31;
            float s = 0.f;
            #pragma unroll
            for (int jj = 0; jj < 16; jj++)
                s += sPair[(half*16 + jj)*D2 + c];
            fb[768 + t] = s * (1.0f/16.0f);
        }
    }
}

// ---------------------------------------------------------------------------
// K3: feats assembly (h_one copy, tile_up/dn, el_ion)
// ---------------------------------------------------------------------------
__global__ void __launch_bounds__(256) k3_assemble(
    const float* __restrict__ h_one,
    const float* __restrict__ h_el_ion,
    float* __restrict__ feats)
{
    __shared__ float sIon[NION*DELION];
    __shared__ float sAvg[2*D1];
    int b = blockIdx.x;
    for (int t = threadIdx.x; t < NION*DELION; t += 256)
        sIon[t] = g_hionm[(size_t)b*NION*DELION + t];
    for (int t = threadIdx.x; t < 2*D1; t += 256)
        sAvg[t] = g_avg[(size_t)b*2*D1 + t];
    __syncthreads();

    int d = threadIdx.x;   // 0..255
    for (int i = 0; i < NEL; i++) {
        float* fb = feats + ((size_t)b*NEL + i)*FEAT;
        const float* ho = h_one + ((size_t)b*NEL + i)*D1;
        fb[d]        = ho[d];
        fb[D1 + d]   = sAvg[d];
        fb[2*D1 + d] = sAvg[D1 + d];
    }

    // el_ion: 32 i x 32 c outputs, 8 ion MACs each
    int c  = threadIdx.x & 31;
    int ig = threadIdx.x >> 5;   // 0..7
    #pragma unroll
    for (int r = 0; r < 4; r++) {
        int i = ig + r*8;
        const float* he = h_el_ion + (((size_t)b*NEL + i)*NION)*DELION;
        float acc = 0.f;
        #pragma unroll
        for (int a = 0; a < NION; a++)
            acc += he[a*DELION + c] * sIon[a*DELION + c];
        feats[((size_t)b*NEL + i)*FEAT + 896 + c] = acc * (1.0f/NION);
    }
}

// ---------------------------------------------------------------------------
extern "C" void kernel_launch(void* const* d_in, const int* in_sizes, int n_in,
                              void* d_out, int out_size)
{
    const float* h_one    = (const float*)d_in[0];
    const float* h_ion    = (const float*)d_in[1];
    const float* h_el_el  = (const float*)d_in[2];
    const float* h_el_ion = (const float*)d_in[3];
    const float* W_hmap   = (const float*)d_in[4];
    const float* b_hmap   = (const float*)d_in[5];
    const float* W_wsame  = (const float*)d_in[6];
    const float* b_wsame  = (const float*)d_in[7];
    const float* W_wdiff  = (const float*)d_in[8];
    const float* b_wdiff  = (const float*)d_in[9];
    const float* W_ion    = (const float*)d_in[10];
    const float* b_ion    = (const float*)d_in[11];

    float* out   = (float*)d_out;
    float* feats = out;                                    // tuple order: (feats, mult)
    float* mult  = out + ((size_t)out_size - MULT_ELEMS);  // == feats + B*NEL*FEAT

    k1_hmap<<<BATCH, 256>>>(h_one, W_hmap, b_hmap);
    k1_ion <<<BATCH, 256>>>(h_ion, W_ion, b_ion);
    k2_pairs<<<BATCH, 256>>>(h_el_el, W_wsame, b_wsame, W_wdiff, b_wdiff,
                             feats, mult);
    k3_assemble<<<BATCH, 256>>>(h_one, h_el_ion, feats);
}

// round 2
// speedup vs baseline: 1.0530x; 1.0530x over previous
#include <cuda_runtime.h>

#define BATCH 1024
#define NEL 32
#define NUP 16
#define NION 8
#define D1 256
#define D2 32
#define DION 64
#define DELION 32
#define EMB 64
#define FEAT 928
#define MULT_ELEMS (BATCH*NEL*NEL*EMB)   // 67108864

__device__ float g_hmapped[BATCH*NEL*EMB];       // 8 MB
__device__ float g_hionm[BATCH*NION*DELION];     // 1 MB
__device__ float g_avg[BATCH*2*D1];              // 2 MB

// rel err ~1e-6 tanh: 2 MUFU + few ALU
__device__ __forceinline__ float fast_tanh(float x) {
    float ax = fabsf(x);
    float e  = __expf(-2.0f * ax);
    float r  = __fdividef(1.0f - e, 1.0f + e);
    return copysignf(r, x);
}

// ---------------------------------------------------------------------------
// K1: h_mapped = tanh(h_one @ W_hmap + b), plus spin averages.
// Register-blocked 4i x 2e per thread; 8 LDS+LDG per 32 FFMA -> FMA-bound.
// ---------------------------------------------------------------------------
__global__ void __launch_bounds__(256, 2) k1_hmap(
    const float* __restrict__ h_one,
    const float* __restrict__ W,      // (256,64)
    const float* __restrict__ bias)   // (64,)
{
    __shared__ __align__(16) float sH[NEL*D1];   // 32 KB
    int b = blockIdx.x;
    const float4* hb4 = (const float4*)(h_one + (size_t)b*NEL*D1);
    #pragma unroll
    for (int t = 0; t < 8; t++)
        ((float4*)sH)[threadIdx.x + t*256] = hb4[threadIdx.x + t*256];
    __syncthreads();

    int et = threadIdx.x & 31;   int e0 = et*2;
    int it = threadIdx.x >> 5;   // rows it*4 .. it*4+3

    float2 bv = __ldg((const float2*)(bias + e0));
    float2 acc[4];
    #pragma unroll
    for (int r = 0; r < 4; r++) acc[r] = bv;

    #pragma unroll 4
    for (int k = 0; k < D1; k += 4) {
        float h[4][4];
        #pragma unroll
        for (int r = 0; r < 4; r++) {
            float4 v = *(const float4*)&sH[(it*4 + r)*D1 + k];
            h[r][0] = v.x; h[r][1] = v.y; h[r][2] = v.z; h[r][3] = v.w;
        }
        #pragma unroll
        for (int t = 0; t < 4; t++) {
            float2 w = __ldg((const float2*)(W + (k + t)*EMB + e0));
            #pragma unroll
            for (int r = 0; r < 4; r++) {
                acc[r].x = fmaf(h[r][t], w.x, acc[r].x);
                acc[r].y = fmaf(h[r][t], w.y, acc[r].y);
            }
        }
    }
    float* o = g_hmapped + (size_t)b*NEL*EMB;
    #pragma unroll
    for (int r = 0; r < 4; r++) {
        float2 ov = make_float2(fast_tanh(acc[r].x), fast_tanh(acc[r].y));
        *(float2*)&o[(it*4 + r)*EMB + e0] = ov;
    }

    // spin-averages of h_one
    int d = threadIdx.x;
    float su = 0.f, sd = 0.f;
    #pragma unroll
    for (int i = 0; i < NUP; i++)  su += sH[i*D1 + d];
    #pragma unroll
    for (int i = NUP; i < NEL; i++) sd += sH[i*D1 + d];
    g_avg[(size_t)b*2*D1 + d]      = su * (1.0f/NUP);
    g_avg[(size_t)b*2*D1 + D1 + d] = sd * (1.0f/(NEL - NUP));
}

// ---------------------------------------------------------------------------
// K1b: h_ion_mapped = tanh(h_ion @ W_ion + b_ion)
// ---------------------------------------------------------------------------
__global__ void __launch_bounds__(256) k1_ion(
    const float* __restrict__ h_ion,
    const float* __restrict__ W,
    const float* __restrict__ bias)
{
    __shared__ float sI[NION*DION];
    int b = blockIdx.x;
    const float* ib = h_ion + (size_t)b*NION*DION;
    for (int t = threadIdx.x; t < NION*DION; t += 256) sI[t] = ib[t];
    __syncthreads();

    int c = threadIdx.x & 31;
    int a = threadIdx.x >> 5;
    float acc = __ldg(bias + c);
    #pragma unroll 4
    for (int k = 0; k < DION; k++)
        acc = fmaf(sI[a*DION + k], __ldg(W + k*DELION + c), acc);
    g_hionm[((size_t)b*NION + a)*DELION + c] = fast_tanh(acc);
}

// ---------------------------------------------------------------------------
// K2: pair GEMM + tanh + multiply -> el_el_mult, el_el, f_pairs.
// Thread tile 2j x 4e, pair rows register-staged: 1 LDS.128 per 8 FFMA.
// sel (same/diff W) is warp-uniform: warp contains jt pair (2w, 2w+1).
// ---------------------------------------------------------------------------
__global__ void __launch_bounds__(256, 2) k2_pairs(
    const float* __restrict__ h_el_el,
    const float* __restrict__ Wsame, const float* __restrict__ bsame,
    const float* __restrict__ Wdiff, const float* __restrict__ bdiff,
    float* __restrict__ feats, float* __restrict__ mult)
{
    __shared__ __align__(16) float sW[2][D2*EMB];      // 16 KB
    __shared__ __align__(16) float sBias[2][EMB];
    __shared__ __align__(16) float sHM[NEL*EMB];       // 8 KB
    __shared__ __align__(16) float sPair[NEL*D2];      // 4 KB
    __shared__ __align__(16) float sRed[16*EMB];       // 4 KB

    int b = blockIdx.x;
    for (int t = threadIdx.x; t < D2*EMB; t += 256) {
        sW[0][t] = Wsame[t];
        sW[1][t] = Wdiff[t];
    }
    if (threadIdx.x < EMB) {
        sBias[0][threadIdx.x] = bsame[threadIdx.x];
        sBias[1][threadIdx.x] = bdiff[threadIdx.x];
    }
    const float* hm = g_hmapped + (size_t)b*NEL*EMB;
    for (int t = threadIdx.x; t < NEL*EMB; t += 256) sHM[t] = hm[t];

    int eg = threadIdx.x & 15;   int e0 = eg*4;
    int jt = threadIdx.x >> 4;   int j0 = jt*2;
    int selbase = (jt < 8) ? 0 : 1;
    const float* pb = h_el_el + (size_t)b*NEL*NEL*D2;

    for (int i = 0; i < NEL; i++) {
        __syncthreads();   // all readers of sPair/sRed from prev iter done
        ((float4*)sPair)[threadIdx.x] =
            ((const float4*)(pb + (size_t)i*NEL*D2))[threadIdx.x];
        __syncthreads();

        int sel = selbase ^ ((i < NUP) ? 0 : 1);
        const float* Wp = sW[sel];

        // stage this thread's two pair rows into registers
        float pr0[D2], pr1[D2];
        #pragma unroll
        for (int q = 0; q < 8; q++) {
            float4 v0 = ((const float4*)sPair)[j0*8 + q];
            float4 v1 = ((const float4*)sPair)[(j0 + 1)*8 + q];
            pr0[q*4+0] = v0.x; pr0[q*4+1] = v0.y; pr0[q*4+2] = v0.z; pr0[q*4+3] = v0.w;
            pr1[q*4+0] = v1.x; pr1[q*4+1] = v1.y; pr1[q*4+2] = v1.z; pr1[q*4+3] = v1.w;
        }

        float4 bv = *(const float4*)&sBias[sel][e0];
        float4 a0 = bv, a1 = bv;
        #pragma unroll
        for (int k = 0; k < D2; k++) {
            float4 wv = *(const float4*)&Wp[k*EMB + e0];
            a0.x = fmaf(pr0[k], wv.x, a0.x);
            a0.y = fmaf(pr0[k], wv.y, a0.y);
            a0.z = fmaf(pr0[k], wv.z, a0.z);
            a0.w = fmaf(pr0[k], wv.w, a0.w);
            a1.x = fmaf(pr1[k], wv.x, a1.x);
            a1.y = fmaf(pr1[k], wv.y, a1.y);
            a1.z = fmaf(pr1[k], wv.z, a1.z);
            a1.w = fmaf(pr1[k], wv.w, a1.w);
        }

        float4 h0 = *(const float4*)&sHM[j0*EMB + e0];
        float4 h1 = *(const float4*)&sHM[(j0 + 1)*EMB + e0];
        float4 o0, o1;
        o0.x = fast_tanh(a0.x)*h0.x; o0.y = fast_tanh(a0.y)*h0.y;
        o0.z = fast_tanh(a0.z)*h0.z; o0.w = fast_tanh(a0.w)*h0.w;
        o1.x = fast_tanh(a1.x)*h1.x; o1.y = fast_tanh(a1.y)*h1.y;
        o1.z = fast_tanh(a1.z)*h1.z; o1.w = fast_tanh(a1.w)*h1.w;

        float* mrow = mult + (((size_t)b*NEL + i)*NEL + j0)*EMB + e0;
        *(float4*)mrow          = o0;
        *(float4*)(mrow + EMB)  = o1;

        float4 s = make_float4(o0.x + o1.x, o0.y + o1.y, o0.z + o1.z, o0.w + o1.w);
        *(float4*)&sRed[jt*EMB + e0] = s;
        __syncthreads();

        float* fb = feats + (((size_t)b*NEL + i)*FEAT);
        if (threadIdx.x < 64) {
            float acc = 0.f;
            #pragma unroll
            for (int g = 0; g < 16; g++) acc += sRed[g*EMB + threadIdx.x];
            fb[832 + threadIdx.x] = acc * (1.0f/16.0f);
        } else if (threadIdx.x < 128) {
            int t = threadIdx.x - 64;
            int half = t >> 5;
            int c = t & 31;
            float sum = 0.f;
            #pragma unroll
            for (int jj = 0; jj < 16; jj++)
                sum += sPair[(half*16 + jj)*D2 + c];
            fb[768 + t] = sum * (1.0f/16.0f);
        }
    }
}

// ---------------------------------------------------------------------------
// K3: feats assembly (h_one copy, tile_up/dn, el_ion)
// ---------------------------------------------------------------------------
__global__ void __launch_bounds__(256) k3_assemble(
    const float* __restrict__ h_one,
    const float* __restrict__ h_el_ion,
    float* __restrict__ feats)
{
    __shared__ float sIon[NION*DELION];
    __shared__ float sAvg[2*D1];
    int b = blockIdx.x;
    for (int t = threadIdx.x; t < NION*DELION; t += 256)
        sIon[t] = g_hionm[(size_t)b*NION*DELION + t];
    for (int t = threadIdx.x; t < 2*D1; t += 256)
        sAvg[t] = g_avg[(size_t)b*2*D1 + t];
    __syncthreads();

    int d = threadIdx.x;
    for (int i = 0; i < NEL; i++) {
        float* fb = feats + ((size_t)b*NEL + i)*FEAT;
        const float* ho = h_one + ((size_t)b*NEL + i)*D1;
        fb[d]        = ho[d];
        fb[D1 + d]   = sAvg[d];
        fb[2*D1 + d] = sAvg[D1 + d];
    }

    int c  = threadIdx.x & 31;
    int ig = threadIdx.x >> 5;
    #pragma unroll
    for (int r = 0; r < 4; r++) {
        int i = ig + r*8;
        const float* he = h_el_ion + (((size_t)b*NEL + i)*NION)*DELION;
        float acc = 0.f;
        #pragma unroll
        for (int a = 0; a < NION; a++)
            acc += he[a*DELION + c] * sIon[a*DELION + c];
        feats[((size_t)b*NEL + i)*FEAT + 896 + c] = acc * (1.0f/NION);
    }
}

// ---------------------------------------------------------------------------
extern "C" void kernel_launch(void* const* d_in, const int* in_sizes, int n_in,
                              void* d_out, int out_size)
{
    const float* h_one    = (const float*)d_in[0];
    const float* h_ion    = (const float*)d_in[1];
    const float* h_el_el  = (const float*)d_in[2];
    const float* h_el_ion = (const float*)d_in[3];
    const float* W_hmap   = (const float*)d_in[4];
    const float* b_hmap   = (const float*)d_in[5];
    const float* W_wsame  = (const float*)d_in[6];
    const float* b_wsame  = (const float*)d_in[7];
    const float* W_wdiff  = (const float*)d_in[8];
    const float* b_wdiff  = (const float*)d_in[9];
    const float* W_ion    = (const float*)d_in[10];
    const float* b_ion    = (const float*)d_in[11];

    float* out   = (float*)d_out;
    float* feats = out;
    float* mult  = out + ((size_t)out_size - MULT_ELEMS);

    k1_hmap<<<BATCH, 256>>>(h_one, W_hmap, b_hmap);
    k1_ion <<<BATCH, 256>>>(h_ion, W_ion, b_ion);
    k2_pairs<<<BATCH, 256>>>(h_el_el, W_wsame, b_wsame, W_wdiff, b_wdiff,
                             feats, mult);
    k3_assemble<<<BATCH, 256>>>(h_one, h_el_ion, feats);
}

// round 6
// speedup vs baseline: 1.2384x; 1.1760x over previous
#include <cuda_runtime.h>
#include <cstdint>

#define BATCH 1024
#define NEL 32
#define NUP 16
#define NION 8
#define D1 256
#define D2 32
#define DION 64
#define DELION 32
#define EMB 64
#define FEAT 928
#define MULT_ELEMS (BATCH*NEL*NEL*EMB)   // 67108864

__device__ float g_hmapped[BATCH*NEL*EMB];       // 8 MB
__device__ float g_avg[BATCH*2*D1];              // 2 MB

// rel err ~1e-6 tanh: 2 MUFU + few ALU
__device__ __forceinline__ float fast_tanh(float x) {
    float ax = fabsf(x);
    float e  = __expf(-2.0f * ax);
    float r  = __fdividef(1.0f - e, 1.0f + e);
    return copysignf(r, x);
}

__device__ __forceinline__ void cp16(void* dst_smem, const void* src) {
    unsigned d = (unsigned)__cvta_generic_to_shared(dst_smem);
    asm volatile("cp.async.cg.shared.global [%0], [%1], 16;\n" :: "r"(d), "l"(src));
}
__device__ __forceinline__ void cp_commit() {
    asm volatile("cp.async.commit_group;\n");
}
__device__ __forceinline__ void cp_wait0() {
    asm volatile("cp.async.wait_group 0;\n" ::: "memory");
}

// ---------------------------------------------------------------------------
// K1: h_mapped = tanh(h_one @ W_hmap + b), plus spin averages.
// ---------------------------------------------------------------------------
__global__ void __launch_bounds__(256, 2) k1_hmap(
    const float* __restrict__ h_one,
    const float* __restrict__ W,      // (256,64)
    const float* __restrict__ bias)   // (64,)
{
    __shared__ __align__(16) float sH[NEL*D1];   // 32 KB
    int b = blockIdx.x;
    const float4* hb4 = (const float4*)(h_one + (size_t)b*NEL*D1);
    #pragma unroll
    for (int t = 0; t < 8; t++)
        ((float4*)sH)[threadIdx.x + t*256] = hb4[threadIdx.x + t*256];
    __syncthreads();

    int et = threadIdx.x & 31;   int e0 = et*2;
    int it = threadIdx.x >> 5;   // rows it*4 .. it*4+3

    float2 bv = __ldg((const float2*)(bias + e0));
    float2 acc[4];
    #pragma unroll
    for (int r = 0; r < 4; r++) acc[r] = bv;

    #pragma unroll 4
    for (int k = 0; k < D1; k += 4) {
        float h[4][4];
        #pragma unroll
        for (int r = 0; r < 4; r++) {
            float4 v = *(const float4*)&sH[(it*4 + r)*D1 + k];
            h[r][0] = v.x; h[r][1] = v.y; h[r][2] = v.z; h[r][3] = v.w;
        }
        #pragma unroll
        for (int t = 0; t < 4; t++) {
            float2 w = __ldg((const float2*)(W + (k + t)*EMB + e0));
            #pragma unroll
            for (int r = 0; r < 4; r++) {
                acc[r].x = fmaf(h[r][t], w.x, acc[r].x);
                acc[r].y = fmaf(h[r][t], w.y, acc[r].y);
            }
        }
    }
    float* o = g_hmapped + (size_t)b*NEL*EMB;
    #pragma unroll
    for (int r = 0; r < 4; r++) {
        float2 ov = make_float2(fast_tanh(acc[r].x), fast_tanh(acc[r].y));
        *(float2*)&o[(it*4 + r)*EMB + e0] = ov;
    }

    int d = threadIdx.x;
    float su = 0.f, sd = 0.f;
    #pragma unroll
    for (int i = 0; i < NUP; i++)  su += sH[i*D1 + d];
    #pragma unroll
    for (int i = NUP; i < NEL; i++) sd += sH[i*D1 + d];
    g_avg[(size_t)b*2*D1 + d]      = su * (1.0f/NUP);
    g_avg[(size_t)b*2*D1 + D1 + d] = sd * (1.0f/(NEL - NUP));
}

// ---------------------------------------------------------------------------
// K2: pair GEMM + tanh + multiply -> el_el_mult, el_el, f_pairs.
// 512 threads/block (2 i-rows per step, 2 blocks/SM = 32 warps),
// cp.async double-buffered tiles, 1 barrier per row, shfl-combined reduction.
// ---------------------------------------------------------------------------
__global__ void __launch_bounds__(512, 2) k2_pairs(
    const float* __restrict__ h_el_el,
    const float* __restrict__ Wsame, const float* __restrict__ bsame,
    const float* __restrict__ Wdiff, const float* __restrict__ bdiff,
    float* __restrict__ feats, float* __restrict__ mult)
{
    __shared__ __align__(16) float sW[2][D2*EMB];        // 16 KB
    __shared__ __align__(16) float sBias[2][EMB];        // 0.5 KB
    __shared__ __align__(16) float sHM[NEL*EMB];         // 8 KB
    __shared__ __align__(16) float sPair[2][2*NEL*D2];   // ping-pong x 2 rows, 16 KB
    __shared__ __align__(16) float sRed[2][8*EMB];       // 4 KB

    int b   = blockIdx.x;
    int tid = threadIdx.x;

    for (int t = tid; t < D2*EMB; t += 512) {
        sW[0][t] = Wsame[t];
        sW[1][t] = Wdiff[t];
    }
    if (tid < EMB) {
        sBias[0][tid] = bsame[tid];
        sBias[1][tid] = bdiff[tid];
    }
    const float* hm = g_hmapped + (size_t)b*NEL*EMB;
    for (int t = tid; t < NEL*EMB; t += 512) sHM[t] = hm[t];

    const float* pb = h_el_el + (size_t)b*NEL*NEL*D2;
    // prefetch rows 0,1 (8KB): 512 threads x 16B
    cp16(&sPair[0][tid*4], pb + tid*4);
    cp_commit();
    cp_wait0();
    __syncthreads();

    int h    = tid >> 8;          // which of the 2 rows this thread computes
    int ht   = tid & 255;
    int eg   = ht & 15;  int e0 = eg*4;
    int jt   = ht >> 4;  int j0 = jt*2;
    int lane = tid & 31;
    int w    = ht >> 5;           // warp index within half, 0..7
    int selbase = (jt < 8) ? 0 : 1;

    for (int s = 0; s < 16; s++) {
        int cur = s & 1;
        if (s < 15) {
            cp16(&sPair[cur ^ 1][tid*4], pb + (size_t)(s + 1)*2*NEL*D2 + tid*4);
            cp_commit();
        }
        int i   = 2*s + h;
        int sel = selbase ^ ((s < 8) ? 0 : 1);   // i<16  <=>  s<8
        const float* Wp   = sW[sel];
        const float* prow = &sPair[cur][h*NEL*D2];

        float4 bv = *(const float4*)&sBias[sel][e0];
        float4 a0 = bv, a1 = bv;
        #pragma unroll
        for (int k = 0; k < D2; k++) {
            float p0 = prow[j0*D2 + k];
            float p1 = prow[j0*D2 + D2 + k];
            float4 wv = *(const float4*)&Wp[k*EMB + e0];
            a0.x = fmaf(p0, wv.x, a0.x);
            a0.y = fmaf(p0, wv.y, a0.y);
            a0.z = fmaf(p0, wv.z, a0.z);
            a0.w = fmaf(p0, wv.w, a0.w);
            a1.x = fmaf(p1, wv.x, a1.x);
            a1.y = fmaf(p1, wv.y, a1.y);
            a1.z = fmaf(p1, wv.z, a1.z);
            a1.w = fmaf(p1, wv.w, a1.w);
        }

        float4 h0 = *(const float4*)&sHM[j0*EMB + e0];
        float4 h1 = *(const float4*)&sHM[(j0 + 1)*EMB + e0];
        float4 o0, o1;
        o0.x = fast_tanh(a0.x)*h0.x; o0.y = fast_tanh(a0.y)*h0.y;
        o0.z = fast_tanh(a0.z)*h0.z; o0.w = fast_tanh(a0.w)*h0.w;
        o1.x = fast_tanh(a1.x)*h1.x; o1.y = fast_tanh(a1.y)*h1.y;
        o1.z = fast_tanh(a1.z)*h1.z; o1.w = fast_tanh(a1.w)*h1.w;

        float* mrow = mult + (((size_t)b*NEL + i)*NEL + j0)*EMB + e0;
        *(float4*)mrow         = o0;
        *(float4*)(mrow + EMB) = o1;

        // partial el_el: sum this thread's two j, then combine the warp's
        // two jt groups via shfl (lanes 0-15 end with the warp partial).
        float4 s4 = make_float4(o0.x + o1.x, o0.y + o1.y,
                                o0.z + o1.z, o0.w + o1.w);
        s4.x += __shfl_down_sync(0xffffffffu, s4.x, 16);
        s4.y += __shfl_down_sync(0xffffffffu, s4.y, 16);
        s4.z += __shfl_down_sync(0xffffffffu, s4.z, 16);
        s4.w += __shfl_down_sync(0xffffffffu, s4.w, 16);
        if (lane < 16)
            *(float4*)&sRed[h][w*EMB + lane*4] = s4;

        if (s < 15) cp_wait0();   // next tiles landed (overlapped with compute)
        __syncthreads();

        // reductions for rows i=2s (hh=0) and i=2s+1 (hh=1)
        if (tid < 128) {
            int hh = tid >> 6;
            int e  = tid & 63;
            float acc = 0.f;
            #pragma unroll
            for (int g = 0; g < 8; g++) acc += sRed[hh][g*EMB + e];
            feats[(((size_t)b*NEL + 2*s + hh)*FEAT) + 832 + e] = acc * (1.0f/16.0f);
        } else if (tid < 256) {
            int t2 = tid - 128;
            int hh = t2 >> 6;
            int t3 = t2 & 63;          // 0..63: [half-spin(1) | c(5)]
            int half = t3 >> 5;
            int c    = t3 & 31;
            const float* tp = &sPair[cur][hh*NEL*D2];
            float sum = 0.f;
            #pragma unroll
            for (int jj = 0; jj < 16; jj++)
                sum += tp[(half*16 + jj)*D2 + c];
            feats[(((size_t)b*NEL + 2*s + hh)*FEAT) + 768 + t3] = sum * (1.0f/16.0f);
        }
        __syncthreads();   // sRed / sPair[cur] consumed before next overwrite
    }
}

// ---------------------------------------------------------------------------
// K3: feats assembly (h_one copy, tile_up/dn, el_ion incl. ion mapping)
// ---------------------------------------------------------------------------
__global__ void __launch_bounds__(256) k3_assemble(
    const float* __restrict__ h_one,
    const float* __restrict__ h_ion,
    const float* __restrict__ h_el_ion,
    const float* __restrict__ W_ion, const float* __restrict__ b_ion,
    float* __restrict__ feats)
{
    __shared__ float sI[NION*DION];
    __shared__ float sIon[NION*DELION];
    __shared__ float sAvg[2*D1];
    int b = blockIdx.x;
    for (int t = threadIdx.x; t < NION*DION; t += 256)
        sI[t] = h_ion[(size_t)b*NION*DION + t];
    for (int t = threadIdx.x; t < 2*D1; t += 256)
        sAvg[t] = g_avg[(size_t)b*2*D1 + t];
    __syncthreads();

    {   // ion mapping: 8 ions x 32 out, 64-k dot each (256 threads = one each)
        int c = threadIdx.x & 31;
        int a = threadIdx.x >> 5;
        float acc = __ldg(b_ion + c);
        #pragma unroll 4
        for (int k = 0; k < DION; k++)
            acc = fmaf(sI[a*DION + k], __ldg(W_ion + k*DELION + c), acc);
        sIon[a*DELION + c] = fast_tanh(acc);
    }
    __syncthreads();

    int d = threadIdx.x;
    for (int i = 0; i < NEL; i++) {
        float* fb = feats + ((size_t)b*NEL + i)*FEAT;
        const float* ho = h_one + ((size_t)b*NEL + i)*D1;
        fb[d]        = ho[d];
        fb[D1 + d]   = sAvg[d];
        fb[2*D1 + d] = sAvg[D1 + d];
    }

    int c  = threadIdx.x & 31;
    int ig = threadIdx.x >> 5;
    #pragma unroll
    for (int r = 0; r < 4; r++) {
        int i = ig + r*8;
        const float* he = h_el_ion + (((size_t)b*NEL + i)*NION)*DELION;
        float acc = 0.f;
        #pragma unroll
        for (int a = 0; a < NION; a++)
            acc += he[a*DELION + c] * sIon[a*DELION + c];
        feats[((size_t)b*NEL + i)*FEAT + 896 + c] = acc * (1.0f/NION);
    }
}

// ---------------------------------------------------------------------------
extern "C" void kernel_launch(void* const* d_in, const int* in_sizes, int n_in,
                              void* d_out, int out_size)
{
    const float* h_one    = (const float*)d_in[0];
    const float* h_ion    = (const float*)d_in[1];
    const float* h_el_el  = (const float*)d_in[2];
    const float* h_el_ion = (const float*)d_in[3];
    const float* W_hmap   = (const float*)d_in[4];
    const float* b_hmap   = (const float*)d_in[5];
    const float* W_wsame  = (const float*)d_in[6];
    const float* b_wsame  = (const float*)d_in[7];
    const float* W_wdiff  = (const float*)d_in[8];
    const float* b_wdiff  = (const float*)d_in[9];
    const float* W_ion    = (const float*)d_in[10];
    const float* b_ion    = (const float*)d_in[11];

    float* out   = (float*)d_out;
    float* feats = out;
    float* mult  = out + ((size_t)out_size - MULT_ELEMS);

    k1_hmap<<<BATCH, 256>>>(h_one, W_hmap, b_hmap);
    k2_pairs<<<BATCH, 512>>>(h_el_el, W_wsame, b_wsame, W_wdiff, b_wdiff,
                             feats, mult);
    k3_assemble<<<BATCH, 256>>>(h_one, h_ion, h_el_ion, W_ion, b_ion, feats);
}

// round 10
// speedup vs baseline: 1.2757x; 1.0302x over previous
#include <cuda_runtime.h>
#include <cstdint>

#define BATCH 1024
#define NEL 32
#define NUP 16
#define NION 8
#define D1 256
#define D2 32
#define DION 64
#define DELION 32
#define EMB 64
#define FEAT 928
#define MULT_ELEMS (BATCH*NEL*NEL*EMB)   // 67108864

__device__ float g_hmapped[BATCH*NEL*EMB];       // 8 MB

// rel err ~1e-6 tanh: 2 MUFU + few ALU
__device__ __forceinline__ float fast_tanh(float x) {
    float ax = fabsf(x);
    float e  = __expf(-2.0f * ax);
    float r  = __fdividef(1.0f - e, 1.0f + e);
    return copysignf(r, x);
}

__device__ __forceinline__ void cp16(void* dst_smem, const void* src) {
    unsigned d = (unsigned)__cvta_generic_to_shared(dst_smem);
    asm volatile("cp.async.cg.shared.global [%0], [%1], 16;\n" :: "r"(d), "l"(src));
}
#define CP_COMMIT() asm volatile("cp.async.commit_group;\n")
#define CP_WAIT0()  asm volatile("cp.async.wait_group 0;\n" ::: "memory")

// ---------------------------------------------------------------------------
// K13: fused h_mapped GEMM + spin averages + ion mapping + feats assembly.
// ---------------------------------------------------------------------------
__global__ void __launch_bounds__(256, 3) k13_fused(
    const float* __restrict__ h_one,
    const float* __restrict__ W,      // (256,64)
    const float* __restrict__ bias,   // (64,)
    const float* __restrict__ h_ion,
    const float* __restrict__ h_el_ion,
    const float* __restrict__ W_ion, const float* __restrict__ b_ion,
    float* __restrict__ feats)
{
    __shared__ __align__(16) float sH[NEL*D1];       // 32 KB
    __shared__ float sI[NION*DION];                  // 2 KB
    __shared__ float sIon[NION*DELION];              // 1 KB
    int b = blockIdx.x;
    const float4* hb4 = (const float4*)(h_one + (size_t)b*NEL*D1);
    #pragma unroll
    for (int t = 0; t < 8; t++)
        ((float4*)sH)[threadIdx.x + t*256] = hb4[threadIdx.x + t*256];
    for (int t = threadIdx.x; t < NION*DION; t += 256)
        sI[t] = h_ion[(size_t)b*NION*DION + t];
    __syncthreads();

    // ion mapping: one (a,c) per thread
    {
        int c = threadIdx.x & 31;
        int a = threadIdx.x >> 5;
        float acc = __ldg(b_ion + c);
        #pragma unroll 4
        for (int k = 0; k < DION; k++)
            acc = fmaf(sI[a*DION + k], __ldg(W_ion + k*DELION + c), acc);
        sIon[a*DELION + c] = fast_tanh(acc);
    }

    // h_mapped GEMM: 4 rows x 2 cols per thread
    int et = threadIdx.x & 31;   int e0 = et*2;
    int it = threadIdx.x >> 5;

    float2 bv = __ldg((const float2*)(bias + e0));
    float2 acc[4];
    #pragma unroll
    for (int r = 0; r < 4; r++) acc[r] = bv;

    #pragma unroll 4
    for (int k = 0; k < D1; k += 4) {
        float h[4][4];
        #pragma unroll
        for (int r = 0; r < 4; r++) {
            float4 v = *(const float4*)&sH[(it*4 + r)*D1 + k];
            h[r][0] = v.x; h[r][1] = v.y; h[r][2] = v.z; h[r][3] = v.w;
        }
        #pragma unroll
        for (int t = 0; t < 4; t++) {
            float2 w = __ldg((const float2*)(W + (k + t)*EMB + e0));
            #pragma unroll
            for (int r = 0; r < 4; r++) {
                acc[r].x = fmaf(h[r][t], w.x, acc[r].x);
                acc[r].y = fmaf(h[r][t], w.y, acc[r].y);
            }
        }
    }
    float* o = g_hmapped + (size_t)b*NEL*EMB;
    #pragma unroll
    for (int r = 0; r < 4; r++) {
        float2 ov = make_float2(fast_tanh(acc[r].x), fast_tanh(acc[r].y));
        *(float2*)&o[(it*4 + r)*EMB + e0] = ov;
    }

    // spin averages of h_one (per-thread feature d)
    int d = threadIdx.x;
    float su = 0.f, sd = 0.f;
    #pragma unroll
    for (int i = 0; i < NUP; i++)  su += sH[i*D1 + d];
    #pragma unroll
    for (int i = NUP; i < NEL; i++) sd += sH[i*D1 + d];
    float au = su * (1.0f/NUP);
    float ad = sd * (1.0f/(NEL - NUP));

    __syncthreads();   // sIon ready

    // feats: h_one copy + tiles
    for (int i = 0; i < NEL; i++) {
        float* fb = feats + ((size_t)b*NEL + i)*FEAT;
        fb[d]        = sH[i*D1 + d];
        fb[D1 + d]   = au;
        fb[2*D1 + d] = ad;
    }

    // el_ion
    int c  = threadIdx.x & 31;
    int ig = threadIdx.x >> 5;
    #pragma unroll
    for (int r = 0; r < 4; r++) {
        int i = ig + r*8;
        const float* he = h_el_ion + (((size_t)b*NEL + i)*NION)*DELION;
        float acc2 = 0.f;
        #pragma unroll
        for (int a = 0; a < NION; a++)
            acc2 += he[a*DELION + c] * sIon[a*DELION + c];
        feats[((size_t)b*NEL + i)*FEAT + 896 + c] = acc2 * (1.0f/NION);
    }
}

// ---------------------------------------------------------------------------
// K2: pair GEMM + tanh + multiply -> el_el_mult, el_el, f_pairs.
// 512 threads (2 i-rows/step), cp.async double-buffered tiles,
// ONE barrier per step (sRed parity double-buffered, f_pairs pre-barrier,
// el_el reduction post-barrier overlaps next step's compute).
// ---------------------------------------------------------------------------
__global__ void __launch_bounds__(512, 2) k2_pairs(
    const float* __restrict__ h_el_el,
    const float* __restrict__ Wsame, const float* __restrict__ bsame,
    const float* __restrict__ Wdiff, const float* __restrict__ bdiff,
    float* __restrict__ feats, float* __restrict__ mult)
{
    __shared__ __align__(16) float sW[2][D2*EMB];        // 16 KB
    __shared__ __align__(16) float sHM[NEL*EMB];         // 8 KB
    __shared__ __align__(16) float sPair[2][2*NEL*D2];   // ping-pong x 2 rows, 16 KB
    __shared__ __align__(16) float sRed[2][2][8*EMB];    // [parity][h][warp*64+e], 8 KB

    int b   = blockIdx.x;
    int tid = threadIdx.x;

    for (int t = tid; t < D2*EMB; t += 512) {
        sW[0][t] = Wsame[t];
        sW[1][t] = Wdiff[t];
    }
    const float* hm = g_hmapped + (size_t)b*NEL*EMB;
    for (int t = tid; t < NEL*EMB; t += 512) sHM[t] = hm[t];

    const float* pb = h_el_el + (size_t)b*NEL*NEL*D2;
    cp16(&sPair[0][tid*4], pb + tid*4);      // rows 0,1
    CP_COMMIT();

    int h    = tid >> 8;          // which of the 2 rows this thread computes
    int ht   = tid & 255;
    int eg   = ht & 15;  int e0 = eg*4;
    int jt   = ht >> 4;  int j0 = jt*2;
    int lane = tid & 31;
    int w    = ht >> 5;           // warp index within half, 0..7
    int selbase = (jt < 8) ? 0 : 1;

    float4 bvS = __ldg((const float4*)(bsame + e0));
    float4 bvD = __ldg((const float4*)(bdiff + e0));

    CP_WAIT0();
    __syncthreads();

    for (int s = 0; s < 16; s++) {
        int cur = s & 1;
        if (s < 15) {
            cp16(&sPair[cur ^ 1][tid*4], pb + (size_t)(s + 1)*2*NEL*D2 + tid*4);
            CP_COMMIT();
        }
        int i   = 2*s + h;
        int sel = selbase ^ ((s < 8) ? 0 : 1);   // i<16  <=>  s<8
        const float* Wp   = sW[sel];
        const float* prow = &sPair[cur][h*NEL*D2];

        float4 bv = sel ? bvD : bvS;
        float4 a0 = bv, a1 = bv;
        #pragma unroll
        for (int k = 0; k < D2; k++) {
            float p0 = prow[j0*D2 + k];
            float p1 = prow[j0*D2 + D2 + k];
            float4 wv = *(const float4*)&Wp[k*EMB + e0];
            a0.x = fmaf(p0, wv.x, a0.x);
            a0.y = fmaf(p0, wv.y, a0.y);
            a0.z = fmaf(p0, wv.z, a0.z);
            a0.w = fmaf(p0, wv.w, a0.w);
            a1.x = fmaf(p1, wv.x, a1.x);
            a1.y = fmaf(p1, wv.y, a1.y);
            a1.z = fmaf(p1, wv.z, a1.z);
            a1.w = fmaf(p1, wv.w, a1.w);
        }

        float4 h0 = *(const float4*)&sHM[j0*EMB + e0];
        float4 h1 = *(const float4*)&sHM[(j0 + 1)*EMB + e0];
        float4 o0, o1;
        o0.x = fast_tanh(a0.x)*h0.x; o0.y = fast_tanh(a0.y)*h0.y;
        o0.z = fast_tanh(a0.z)*h0.z; o0.w = fast_tanh(a0.w)*h0.w;
        o1.x = fast_tanh(a1.x)*h1.x; o1.y = fast_tanh(a1.y)*h1.y;
        o1.z = fast_tanh(a1.z)*h1.z; o1.w = fast_tanh(a1.w)*h1.w;

        float* mrow = mult + (((size_t)b*NEL + i)*NEL + j0)*EMB + e0;
        *(float4*)mrow         = o0;
        *(float4*)(mrow + EMB) = o1;

        // el_el partials: combine the warp's two jt groups via shfl
        float4 s4 = make_float4(o0.x + o1.x, o0.y + o1.y,
                                o0.z + o1.z, o0.w + o1.w);
        s4.x += __shfl_down_sync(0xffffffffu, s4.x, 16);
        s4.y += __shfl_down_sync(0xffffffffu, s4.y, 16);
        s4.z += __shfl_down_sync(0xffffffffu, s4.z, 16);
        s4.w += __shfl_down_sync(0xffffffffu, s4.w, 16);
        if (lane < 16)
            *(float4*)&sRed[cur][h][w*EMB + lane*4] = s4;

        // f_pairs (pre-barrier; reads current tile, protected by prev barrier)
        if (tid < 128) {
            int hh   = tid >> 6;
            int t3   = tid & 63;
            int half = t3 >> 5;
            int c    = t3 & 31;
            const float* tp = &sPair[cur][hh*NEL*D2];
            float sum = 0.f;
            #pragma unroll
            for (int jj = 0; jj < 16; jj++)
                sum += tp[(half*16 + jj)*D2 + c];
            feats[(((size_t)b*NEL + 2*s + hh)*FEAT) + 768 + t3] = sum * (1.0f/16.0f);
        }

        if (s < 15) CP_WAIT0();   // next tiles landed (overlapped with compute)
        __syncthreads();          // sRed[cur] complete; sPair[cur^1] visible

        // el_el reduction (overlaps other warps' next-step compute)
        if (tid < 128) {
            int hh = tid >> 6;
            int e  = tid & 63;
            float acc = 0.f;
            #pragma unroll
            for (int g = 0; g < 8; g++) acc += sRed[cur][hh][g*EMB + e];
            feats[(((size_t)b*NEL + 2*s + hh)*FEAT) + 832 + e] = acc * (1.0f/16.0f);
        }
    }
}

// ---------------------------------------------------------------------------
extern "C" void kernel_launch(void* const* d_in, const int* in_sizes, int n_in,
                              void* d_out, int out_size)
{
    const float* h_one    = (const float*)d_in[0];
    const float* h_ion    = (const float*)d_in[1];
    const float* h_el_el  = (const float*)d_in[2];
    const float* h_el_ion = (const float*)d_in[3];
    const float* W_hmap   = (const float*)d_in[4];
    const float* b_hmap   = (const float*)d_in[5];
    const float* W_wsame  = (const float*)d_in[6];
    const float* b_wsame  = (const float*)d_in[7];
    const float* W_wdiff  = (const float*)d_in[8];
    const float* b_wdiff  = (const float*)d_in[9];
    const float* W_ion    = (const float*)d_in[10];
    const float* b_ion    = (const float*)d_in[11];

    float* out   = (float*)d_out;
    float* feats = out;
    float* mult  = out + ((size_t)out_size - MULT_ELEMS);

    k13_fused<<<BATCH, 256>>>(h_one, W_hmap, b_hmap, h_ion, h_el_ion,
                              W_ion, b_ion, feats);
    k2_pairs<<<BATCH, 512>>>(h_el_el, W_wsame, b_wsame, W_wdiff, b_wdiff,
                             feats, mult);
}

// round 11
// speedup vs baseline: 1.3666x; 1.0713x over previous
#include <cuda_runtime.h>
#include <cstdint>

#define BATCH 1024
#define NEL 32
#define NUP 16
#define NION 8
#define D1 256
#define D2 32
#define DION 64
#define DELION 32
#define EMB 64
#define FEAT 928
#define MULT_ELEMS (BATCH*NEL*NEL*EMB)   // 67108864

// K13 dynamic smem layout (floats)
#define K13_SH    0          // 32*257 = 8224 (row-padded h_one)
#define K13_SW    8224       // 16384 (W_hmap)
#define K13_SI    24608      // 512 (h_ion)
#define K13_SION  25120      // 256 (ion mapped)
#define K13_SMEM_BYTES ((25120 + 256) * 4)          // 101504

// K2 dynamic smem layout (floats)
#define K2_SW     0          // [2][2048] = 4096
#define K2_SHM    4096       // 2048
#define K2_SRED   6144       // [2][4][4][64] = 2048
#define K2_SPAIR  8192       // 2 x (4 rows x 32 j x 36 k) = 2*4608
#define K2_ROWPAD 36
#define K2_TILE   4608       // 4*32*36
#define K2_SMEM_BYTES ((8192 + 2*4608) * 4)         // 69632

__device__ float g_hmapped[BATCH*NEL*EMB];       // 8 MB

// rel err ~1e-6 tanh: 2 MUFU + few ALU
__device__ __forceinline__ float fast_tanh(float x) {
    float ax = fabsf(x);
    float e  = __expf(-2.0f * ax);
    float r  = __fdividef(1.0f - e, 1.0f + e);
    return copysignf(r, x);
}

__device__ __forceinline__ void cp16(void* dst_smem, const void* src) {
    unsigned d = (unsigned)__cvta_generic_to_shared(dst_smem);
    asm volatile("cp.async.cg.shared.global [%0], [%1], 16;\n" :: "r"(d), "l"(src));
}
#define CP_COMMIT() asm volatile("cp.async.commit_group;\n")
#define CP_WAIT0()  asm volatile("cp.async.wait_group 0;\n" ::: "memory")

// ---------------------------------------------------------------------------
// K13: fused h_mapped GEMM + spin averages + ion mapping + feats assembly.
// GEMM layout: warp w owns e-columns [w*8, w*8+8), lane = i-row.
// h via conflict-free LDS.32 (row pad 257); W via warp-broadcast LDS.128.
// ---------------------------------------------------------------------------
__global__ void __launch_bounds__(256, 2) k13_fused(
    const float* __restrict__ h_one,
    const float* __restrict__ W,      // (256,64)
    const float* __restrict__ bias,   // (64,)
    const float* __restrict__ h_ion,
    const float* __restrict__ h_el_ion,
    const float* __restrict__ W_ion, const float* __restrict__ b_ion,
    float* __restrict__ feats)
{
    extern __shared__ __align__(16) float smf[];
    float* sH   = smf + K13_SH;
    float* sWm  = smf + K13_SW;
    float* sI   = smf + K13_SI;
    float* sIon = smf + K13_SION;

    int tid = threadIdx.x;
    int b   = blockIdx.x;

    // load h_one (padded rows, 257)
    const float4* hb4 = (const float4*)(h_one + (size_t)b*NEL*D1);
    #pragma unroll
    for (int p = 0; p < 8; p++) {
        int q   = tid + p*256;          // 0..2047 float4 units
        float4 v = hb4[q];
        int row = q >> 6, col = (q & 63)*4;
        float* d = &sH[row*257 + col];
        d[0] = v.x; d[1] = v.y; d[2] = v.z; d[3] = v.w;
    }
    // load W into smem (64KB)
    const float4* W4 = (const float4*)W;
    #pragma unroll
    for (int p = 0; p < 16; p++)
        ((float4*)sWm)[tid + p*256] = W4[tid + p*256];
    for (int t = tid; t < NION*DION; t += 256)
        sI[t] = h_ion[(size_t)b*NION*DION + t];
    __syncthreads();

    // ion mapping: one (a,c) per thread
    {
        int c = tid & 31;
        int a = tid >> 5;
        float acc = __ldg(b_ion + c);
        #pragma unroll 4
        for (int k = 0; k < DION; k++)
            acc = fmaf(sI[a*DION + k], __ldg(W_ion + k*DELION + c), acc);
        sIon[a*DELION + c] = fast_tanh(acc);
    }

    // h_mapped GEMM: warp = e-group, lane = i-row; 8 e per thread
    {
        int w  = tid >> 5;      // 0..7
        int i  = tid & 31;
        int e0 = w*8;
        float4 a0 = __ldg((const float4*)(bias + e0));
        float4 a1 = __ldg((const float4*)(bias + e0 + 4));
        const float* hrow = &sH[i*257];
        #pragma unroll 2
        for (int k = 0; k < D1; k++) {
            float hv = hrow[k];
            float4 w0 = *(const float4*)&sWm[k*EMB + e0];
            float4 w1 = *(const float4*)&sWm[k*EMB + e0 + 4];
            a0.x = fmaf(hv, w0.x, a0.x); a0.y = fmaf(hv, w0.y, a0.y);
            a0.z = fmaf(hv, w0.z, a0.z); a0.w = fmaf(hv, w0.w, a0.w);
            a1.x = fmaf(hv, w1.x, a1.x); a1.y = fmaf(hv, w1.y, a1.y);
            a1.z = fmaf(hv, w1.z, a1.z); a1.w = fmaf(hv, w1.w, a1.w);
        }
        float4 o0, o1;
        o0.x = fast_tanh(a0.x); o0.y = fast_tanh(a0.y);
        o0.z = fast_tanh(a0.z); o0.w = fast_tanh(a0.w);
        o1.x = fast_tanh(a1.x); o1.y = fast_tanh(a1.y);
        o1.z = fast_tanh(a1.z); o1.w = fast_tanh(a1.w);
        float* o = g_hmapped + (size_t)b*NEL*EMB + i*EMB + e0;
        *(float4*)o       = o0;
        *(float4*)(o + 4) = o1;
    }

    // spin averages of h_one (per-thread feature d)
    int d = tid;
    float su = 0.f, sd = 0.f;
    #pragma unroll
    for (int i = 0; i < NUP; i++)  su += sH[i*257 + d];
    #pragma unroll
    for (int i = NUP; i < NEL; i++) sd += sH[i*257 + d];
    float au = su * (1.0f/NUP);
    float ad = sd * (1.0f/(NEL - NUP));

    __syncthreads();   // sIon ready

    // feats: h_one copy + tiles
    for (int i = 0; i < NEL; i++) {
        float* fb = feats + ((size_t)b*NEL + i)*FEAT;
        fb[d]        = sH[i*257 + d];
        fb[D1 + d]   = au;
        fb[2*D1 + d] = ad;
    }

    // el_ion
    int c  = tid & 31;
    int ig = tid >> 5;
    #pragma unroll
    for (int r = 0; r < 4; r++) {
        int i = ig + r*8;
        const float* he = h_el_ion + (((size_t)b*NEL + i)*NION)*DELION;
        float acc2 = 0.f;
        #pragma unroll
        for (int a = 0; a < NION; a++)
            acc2 += he[a*DELION + c] * sIon[a*DELION + c];
        feats[((size_t)b*NEL + i)*FEAT + 896 + c] = acc2 * (1.0f/NION);
    }
}

// ---------------------------------------------------------------------------
// K2: pair GEMM + tanh + multiply -> el_el_mult, el_el, f_pairs.
// 512 threads, 4 i-rows/step (8 steps), thread tile 4j x 4e:
// per k = 4 bank-split broadcasts + 2 W wavefronts vs 16 FFMA -> FMA-bound.
// Pair rows padded to 36 floats (jt-pair banks differ by 16).
// ---------------------------------------------------------------------------
__global__ void __launch_bounds__(512, 2) k2_pairs(
    const float* __restrict__ h_el_el,
    const float* __restrict__ Wsame, const float* __restrict__ bsame,
    const float* __restrict__ Wdiff, const float* __restrict__ bdiff,
    float* __restrict__ feats, float* __restrict__ mult)
{
    extern __shared__ __align__(16) float smf[];
    float* sW    = smf + K2_SW;      // [2][2048]
    float* sHM   = smf + K2_SHM;     // [32][64]
    float* sRed  = smf + K2_SRED;    // [2][4][4][64]
    float* sPair = smf + K2_SPAIR;   // [2][4][32][36]

    int b   = blockIdx.x;
    int tid = threadIdx.x;

    for (int t = tid; t < D2*EMB; t += 512) {
        sW[t]        = Wsame[t];
        sW[2048 + t] = Wdiff[t];
    }
    const float* hm = g_hmapped + (size_t)b*NEL*EMB;
    for (int t = tid; t < NEL*EMB; t += 512) sHM[t] = hm[t];

    const float* pb = h_el_el + (size_t)b*NEL*NEL*D2;
    // prefetch tile 0: rows i=0..3 (16KB) into padded layout
    #pragma unroll
    for (int it = 0; it < 2; it++) {
        int q   = tid + it*512;            // 0..1023 float4 units
        int row = q >> 3, part = q & 7;    // row = h*32 + j
        cp16(&sPair[row*K2_ROWPAD + part*4], pb + (size_t)q*4);
    }
    CP_COMMIT();

    int h  = tid >> 7;          // i within quad
    int ht = tid & 127;
    int eg = ht & 15;  int e0 = eg*4;
    int jt = ht >> 4;  int j0 = jt*4;     // jt 0..7
    int lane = tid & 31;
    int w2   = ht >> 5;         // 0..3: warp within the h-half
    int selbase = (jt < 4) ? 0 : 1;

    float4 bvS = __ldg((const float4*)(bsame + e0));
    float4 bvD = __ldg((const float4*)(bdiff + e0));

    CP_WAIT0();
    __syncthreads();

    for (int s = 0; s < 8; s++) {
        int cur = s & 1;
        if (s < 7) {
            const float* src = pb + (size_t)(s + 1)*4*NEL*D2;
            float* dst = &sPair[(cur ^ 1)*K2_TILE];
            #pragma unroll
            for (int it = 0; it < 2; it++) {
                int q   = tid + it*512;
                int row = q >> 3, part = q & 7;
                cp16(&dst[row*K2_ROWPAD + part*4], src + (size_t)q*4);
            }
            CP_COMMIT();
        }
        int i   = 4*s + h;
        int sel = selbase ^ ((s < 4) ? 0 : 1);   // i<16 <=> s<4
        const float* Wp   = sW + sel*2048;
        const float* prow = &sPair[cur*K2_TILE + h*NEL*K2_ROWPAD + j0*K2_ROWPAD];

        float4 bv = sel ? bvD : bvS;
        float4 a0 = bv, a1 = bv, a2 = bv, a3 = bv;
        #pragma unroll 8
        for (int k = 0; k < D2; k++) {
            float4 wv = *(const float4*)&Wp[k*EMB + e0];
            float p0 = prow[k];
            float p1 = prow[K2_ROWPAD + k];
            float p2 = prow[2*K2_ROWPAD + k];
            float p3 = prow[3*K2_ROWPAD + k];
            a0.x = fmaf(p0, wv.x, a0.x); a0.y = fmaf(p0, wv.y, a0.y);
            a0.z = fmaf(p0, wv.z, a0.z); a0.w = fmaf(p0, wv.w, a0.w);
            a1.x = fmaf(p1, wv.x, a1.x); a1.y = fmaf(p1, wv.y, a1.y);
            a1.z = fmaf(p1, wv.z, a1.z); a1.w = fmaf(p1, wv.w, a1.w);
            a2.x = fmaf(p2, wv.x, a2.x); a2.y = fmaf(p2, wv.y, a2.y);
            a2.z = fmaf(p2, wv.z, a2.z); a2.w = fmaf(p2, wv.w, a2.w);
            a3.x = fmaf(p3, wv.x, a3.x); a3.y = fmaf(p3, wv.y, a3.y);
            a3.z = fmaf(p3, wv.z, a3.z); a3.w = fmaf(p3, wv.w, a3.w);
        }

        // epilogue: tanh * hm, store mult, accumulate el_el partial
        float4 s4 = make_float4(0.f, 0.f, 0.f, 0.f);
        float* mrow = mult + (((size_t)b*NEL + i)*NEL + j0)*EMB + e0;
        float4 av[4] = {a0, a1, a2, a3};
        #pragma unroll
        for (int jj = 0; jj < 4; jj++) {
            float4 hm4 = *(const float4*)&sHM[(j0 + jj)*EMB + e0];
            float4 o;
            o.x = fast_tanh(av[jj].x)*hm4.x;
            o.y = fast_tanh(av[jj].y)*hm4.y;
            o.z = fast_tanh(av[jj].z)*hm4.z;
            o.w = fast_tanh(av[jj].w)*hm4.w;
            *(float4*)(mrow + jj*EMB) = o;
            s4.x += o.x; s4.y += o.y; s4.z += o.z; s4.w += o.w;
        }
        // combine warp's jt pair (lanes 16-31 -> 0-15)
        s4.x += __shfl_down_sync(0xffffffffu, s4.x, 16);
        s4.y += __shfl_down_sync(0xffffffffu, s4.y, 16);
        s4.z += __shfl_down_sync(0xffffffffu, s4.z, 16);
        s4.w += __shfl_down_sync(0xffffffffu, s4.w, 16);
        if (lane < 16)
            *(float4*)&sRed[(((cur*4 + h)*4) + w2)*EMB + lane*4] = s4;

        // f_pairs (pre-barrier; raw tile reads)
        if (tid >= 256) {
            int t    = tid - 256;
            int hh   = t >> 6;
            int t3   = t & 63;
            int half = t3 >> 5;
            int cc   = t3 & 31;
            const float* tp = &sPair[cur*K2_TILE + hh*NEL*K2_ROWPAD];
            float sum = 0.f;
            #pragma unroll
            for (int jj = 0; jj < 16; jj++)
                sum += tp[(half*16 + jj)*K2_ROWPAD + cc];
            feats[(((size_t)b*NEL + 4*s + hh)*FEAT) + 768 + t3] = sum * (1.0f/16.0f);
        }

        if (s < 7) CP_WAIT0();
        __syncthreads();

        // el_el (post-barrier, overlaps next step's compute in other warps)
        if (tid < 256) {
            int hh = tid >> 6;
            int e  = tid & 63;
            float acc = sRed[((cur*4 + hh)*4 + 0)*EMB + e]
                      + sRed[((cur*4 + hh)*4 + 1)*EMB + e]
                      + sRed[((cur*4 + hh)*4 + 2)*EMB + e]
                      + sRed[((cur*4 + hh)*4 + 3)*EMB + e];
            feats[(((size_t)b*NEL + 4*s + hh)*FEAT) + 832 + e] = acc * (1.0f/16.0f);
        }
    }
}

// ---------------------------------------------------------------------------
extern "C" void kernel_launch(void* const* d_in, const int* in_sizes, int n_in,
                              void* d_out, int out_size)
{
    const float* h_one    = (const float*)d_in[0];
    const float* h_ion    = (const float*)d_in[1];
    const float* h_el_el  = (const float*)d_in[2];
    const float* h_el_ion = (const float*)d_in[3];
    const float* W_hmap   = (const float*)d_in[4];
    const float* b_hmap   = (const float*)d_in[5];
    const float* W_wsame  = (const float*)d_in[6];
    const float* b_wsame  = (const float*)d_in[7];
    const float* W_wdiff  = (const float*)d_in[8];
    const float* b_wdiff  = (const float*)d_in[9];
    const float* W_ion    = (const float*)d_in[10];
    const float* b_ion    = (const float*)d_in[11];

    float* out   = (float*)d_out;
    float* feats = out;
    float* mult  = out + ((size_t)out_size - MULT_ELEMS);

    // idempotent, capture-safe (not a stream op, no allocation)
    cudaFuncSetAttribute(k13_fused, cudaFuncAttributeMaxDynamicSharedMemorySize,
                         K13_SMEM_BYTES);
    cudaFuncSetAttribute(k2_pairs, cudaFuncAttributeMaxDynamicSharedMemorySize,
                         K2_SMEM_BYTES);

    k13_fused<<<BATCH, 256, K13_SMEM_BYTES>>>(h_one, W_hmap, b_hmap, h_ion,
                                              h_el_ion, W_ion, b_ion, feats);
    k2_pairs<<<BATCH, 512, K2_SMEM_BYTES>>>(h_el_el, W_wsame, b_wsame,
                                            W_wdiff, b_wdiff, feats, mult);
}